// round 2
// baseline (speedup 1.0000x reference)
#include <cuda_runtime.h>

#define B_  2
#define S_  2048
#define D_  1024
#define H_  16
#define DH_ 64
#define NEGV -1000000000.0f

// Scratch (static __device__ — allocation-free per harness rules)
__device__ float g_Q[B_*S_*D_];
__device__ float g_K[B_*S_*D_];
__device__ float g_V[B_*S_*D_];
__device__ float g_O[B_*S_*D_];

// ---------------------------------------------------------------------------
// SGEMM:  Y[M,N] = X[M,K] * W[N,K]^T   (both operands K-major row-major)
// M=4096, N=K=1024. 128x128 tile, BK=16, 256 threads, 8x8 microtile.
// ---------------------------------------------------------------------------
#define GM 4096
#define GN 1024
#define GK 1024
#define BM 128
#define BN 128
#define BK 16

__global__ __launch_bounds__(256) void sgemm_nt(const float* __restrict__ X,
                                                const float* __restrict__ W,
                                                float* __restrict__ Y) {
    __shared__ float As[BK][BM];
    __shared__ float Bs[BK][BN];
    const int t  = threadIdx.x;
    const int tx = t & 15;
    const int ty = t >> 4;
    const float* Xb = X + (size_t)blockIdx.y * BM * GK;
    const float* Wb = W + (size_t)blockIdx.x * BN * GK;

    float acc[8][8];
#pragma unroll
    for (int i = 0; i < 8; i++)
#pragma unroll
        for (int j = 0; j < 8; j++) acc[i][j] = 0.0f;

    for (int k0 = 0; k0 < GK; k0 += BK) {
#pragma unroll
        for (int r = 0; r < 2; r++) {
            int idx = t + r * 256;          // 0..511
            int row = idx >> 2;             // 0..127
            int kq  = (idx & 3) << 2;       // 0,4,8,12
            float4 a = *(const float4*)(Xb + (size_t)row * GK + k0 + kq);
            As[kq + 0][row] = a.x; As[kq + 1][row] = a.y;
            As[kq + 2][row] = a.z; As[kq + 3][row] = a.w;
            float4 b = *(const float4*)(Wb + (size_t)row * GK + k0 + kq);
            Bs[kq + 0][row] = b.x; Bs[kq + 1][row] = b.y;
            Bs[kq + 2][row] = b.z; Bs[kq + 3][row] = b.w;
        }
        __syncthreads();
#pragma unroll
        for (int kk = 0; kk < BK; kk++) {
            float ra[8], rb[8];
            *(float4*)&ra[0] = *(const float4*)&As[kk][ty * 8];
            *(float4*)&ra[4] = *(const float4*)&As[kk][ty * 8 + 4];
            *(float4*)&rb[0] = *(const float4*)&Bs[kk][tx * 8];
            *(float4*)&rb[4] = *(const float4*)&Bs[kk][tx * 8 + 4];
#pragma unroll
            for (int i = 0; i < 8; i++)
#pragma unroll
                for (int j = 0; j < 8; j++)
                    acc[i][j] += ra[i] * rb[j];
        }
        __syncthreads();
    }

    float* Yb = Y + (size_t)(blockIdx.y * BM + ty * 8) * GN + blockIdx.x * BN + tx * 8;
#pragma unroll
    for (int i = 0; i < 8; i++) {
        *(float4*)(Yb + (size_t)i * GN)     = make_float4(acc[i][0], acc[i][1], acc[i][2], acc[i][3]);
        *(float4*)(Yb + (size_t)i * GN + 4) = make_float4(acc[i][4], acc[i][5], acc[i][6], acc[i][7]);
    }
}

// ---------------------------------------------------------------------------
// Flash-style attention. One block = 128 query rows of one (b,h).
// Two-pass tile softmax: scores staged in padded SMEM so the O rescale
// happens once per 64-key tile. Causal/pad masking by skipping (exact:
// expf(-1e9 - m) == 0.0f in fp32, matching the reference's additive NEG).
// ---------------------------------------------------------------------------
#define AR 128   // query rows per block
#define AK 64    // key tile

__global__ __launch_bounds__(128) void attn_kernel(const float* __restrict__ gQ,
                                                   const float* __restrict__ gK,
                                                   const float* __restrict__ gV,
                                                   const int*   __restrict__ mask,
                                                   float* __restrict__ gO) {
    extern __shared__ float sm[];
    float* Ks  = sm;                        // AK*DH_  = 4096 f
    float* Vs  = Ks + AK * DH_;             // AK*DH_  = 4096 f
    float* Ssh = Vs + AK * DH_;             // AR*(AK+1) = 8320 f (pad -> conflict-free)
    float* Msk = Ssh + AR * (AK + 1);       // AK

    const int t  = threadIdx.x;
    const int h  = blockIdx.y;
    const int b  = blockIdx.z;
    const int r0 = blockIdx.x * AR;
    const int i  = r0 + t;

    const float* qrow = gQ + ((size_t)(b * S_ + i)) * D_ + h * DH_;
    float4 qv[16], ov[16];
#pragma unroll
    for (int x = 0; x < 16; x++) {
        qv[x] = ((const float4*)qrow)[x];
        ov[x] = make_float4(0.f, 0.f, 0.f, 0.f);
    }
    float m = -1e30f, l = 0.0f;

    for (int t0 = 0; t0 < r0 + AR; t0 += AK) {
        // cooperative K/V tile load (coalesced: 16 threads span one 256B row)
        for (int idx = t; idx < AK * (DH_ / 4); idx += 128) {
            int row = idx >> 4;
            int c4  = idx & 15;
            size_t base = ((size_t)(b * S_ + t0 + row)) * D_ + h * DH_;
            ((float4*)(Ks + row * DH_))[c4] = ((const float4*)(gK + base))[c4];
            ((float4*)(Vs + row * DH_))[c4] = ((const float4*)(gV + base))[c4];
        }
        if (t < AK) Msk[t] = (mask[b * S_ + t0 + t] == 0) ? NEGV : 0.0f;
        __syncthreads();

        int jend = i - t0 + 1;
        if (jend > AK) jend = AK;            // <=0 means tile fully causal-blocked

        // pass 1: scores + tile max
        float tm = -1e30f;
        for (int j = 0; j < jend; j++) {
            const float4* kr = (const float4*)(Ks + j * DH_);
            float s0 = 0.f, s1 = 0.f, s2 = 0.f, s3 = 0.f;
#pragma unroll
            for (int x = 0; x < 16; x++) {
                float4 kk = kr[x];
                s0 += qv[x].x * kk.x; s1 += qv[x].y * kk.y;
                s2 += qv[x].z * kk.z; s3 += qv[x].w * kk.w;
            }
            float s = ((s0 + s1) + (s2 + s3)) * 0.125f + Msk[j];
            Ssh[t * (AK + 1) + j] = s;
            tm = fmaxf(tm, s);
        }

        // single rescale per tile
        float mnew = fmaxf(m, tm);
        float corr = __expf(m - mnew);       // first tile: expf(-1e30) == 0, l==0 anyway
        l *= corr;
#pragma unroll
        for (int x = 0; x < 16; x++) {
            ov[x].x *= corr; ov[x].y *= corr; ov[x].z *= corr; ov[x].w *= corr;
        }
        m = mnew;

        // pass 2: p and PV accumulate
        for (int j = 0; j < jend; j++) {
            float p = __expf(Ssh[t * (AK + 1) + j] - m);
            l += p;
            const float4* vr = (const float4*)(Vs + j * DH_);
#pragma unroll
            for (int x = 0; x < 16; x++) {
                float4 vv = vr[x];
                ov[x].x += p * vv.x; ov[x].y += p * vv.y;
                ov[x].z += p * vv.z; ov[x].w += p * vv.w;
            }
        }
        __syncthreads();
    }

    float inv = 1.0f / l;
    float* orow = gO + ((size_t)(b * S_ + i)) * D_ + h * DH_;
#pragma unroll
    for (int x = 0; x < 16; x++) {
        ((float4*)orow)[x] = make_float4(ov[x].x * inv, ov[x].y * inv,
                                         ov[x].z * inv, ov[x].w * inv);
    }
}

// ---------------------------------------------------------------------------
extern "C" void kernel_launch(void* const* d_in, const int* in_sizes, int n_in,
                              void* d_out, int out_size) {
    const float* q    = (const float*)d_in[0];
    const float* k    = (const float*)d_in[1];
    const float* v    = (const float*)d_in[2];
    const int*   mask = (const int*)  d_in[3];
    const float* Wq   = (const float*)d_in[4];
    const float* Wk   = (const float*)d_in[5];
    const float* Wv   = (const float*)d_in[6];
    const float* Wo   = (const float*)d_in[7];
    float* out = (float*)d_out;

    float *Qp, *Kp, *Vp, *Op;
    cudaGetSymbolAddress((void**)&Qp, g_Q);
    cudaGetSymbolAddress((void**)&Kp, g_K);
    cudaGetSymbolAddress((void**)&Vp, g_V);
    cudaGetSymbolAddress((void**)&Op, g_O);

    dim3 ggrid(GN / BN, GM / BM);   // (8, 32)

    sgemm_nt<<<ggrid, 256>>>(q, Wq, Qp);
    sgemm_nt<<<ggrid, 256>>>(k, Wk, Kp);
    sgemm_nt<<<ggrid, 256>>>(v, Wv, Vp);

    size_t smem = (size_t)(2 * AK * DH_ + AR * (AK + 1) + AK) * sizeof(float);
    cudaFuncSetAttribute(attn_kernel, cudaFuncAttributeMaxDynamicSharedMemorySize, (int)smem);
    attn_kernel<<<dim3(S_ / AR, H_, B_), 128, smem>>>(Qp, Kp, Vp, mask, Op);

    sgemm_nt<<<ggrid, 256>>>(Op, Wo, out);
}

// round 6
// speedup vs baseline: 1.3062x; 1.3062x over previous
#include <cuda_runtime.h>

#define B_  2
#define S_  2048
#define D_  1024
#define H_  16
#define DH_ 64
#define NEGV -1000000000.0f

// Scratch (static __device__ — allocation-free per harness rules)
__device__ float g_Q[B_*S_*D_];
__device__ float g_K[B_*S_*D_];
__device__ float g_V[B_*S_*D_];
__device__ float g_O[B_*S_*D_];

// ---------------------------------------------------------------------------
// SGEMM:  Y[M,N] = X[M,K] * W[N,K]^T
// 128x128 tile, BK=16, 256 threads, 8x8 microtile (cols split tx*4 / 64+tx*4
// to avoid 4-way LDS bank conflicts), padded smem stride, reg double-buffer.
// ---------------------------------------------------------------------------
#define GM 4096
#define GN 1024
#define GK 1024
#define BM 128
#define BN 128
#define BK 16
#define GST 132   // padded smem stride

__global__ __launch_bounds__(256) void sgemm_nt(const float* __restrict__ X,
                                                const float* __restrict__ W,
                                                float* __restrict__ Y) {
    __shared__ float As[BK][GST];
    __shared__ float Bs[BK][GST];
    const int t  = threadIdx.x;
    const int tx = t & 15;
    const int ty = t >> 4;
    const float* Xb = X + (size_t)blockIdx.y * BM * GK;
    const float* Wb = W + (size_t)blockIdx.x * BN * GK;

    const int lrow = t >> 2;          // 0..63
    const int lkq  = (t & 3) << 2;    // 0,4,8,12

    float acc[8][8];
#pragma unroll
    for (int i = 0; i < 8; i++)
#pragma unroll
        for (int j = 0; j < 8; j++) acc[i][j] = 0.0f;

    // first tile -> smem
#pragma unroll
    for (int r = 0; r < 2; r++) {
        int row = lrow + r * 64;
        float4 a = *(const float4*)(Xb + (size_t)row * GK + lkq);
        float4 b = *(const float4*)(Wb + (size_t)row * GK + lkq);
        As[lkq+0][row]=a.x; As[lkq+1][row]=a.y; As[lkq+2][row]=a.z; As[lkq+3][row]=a.w;
        Bs[lkq+0][row]=b.x; Bs[lkq+1][row]=b.y; Bs[lkq+2][row]=b.z; Bs[lkq+3][row]=b.w;
    }
    __syncthreads();

    float4 pa[2], pb[2];
    for (int k0 = 0; k0 < GK; k0 += BK) {
        const bool more = (k0 + BK) < GK;
        if (more) {
#pragma unroll
            for (int r = 0; r < 2; r++) {
                int row = lrow + r * 64;
                pa[r] = *(const float4*)(Xb + (size_t)row * GK + k0 + BK + lkq);
                pb[r] = *(const float4*)(Wb + (size_t)row * GK + k0 + BK + lkq);
            }
        }
#pragma unroll
        for (int kk = 0; kk < BK; kk++) {
            float ra[8], rb[8];
            *(float4*)&ra[0] = *(const float4*)&As[kk][ty*8];
            *(float4*)&ra[4] = *(const float4*)&As[kk][ty*8+4];
            *(float4*)&rb[0] = *(const float4*)&Bs[kk][tx*4];
            *(float4*)&rb[4] = *(const float4*)&Bs[kk][64 + tx*4];
#pragma unroll
            for (int i = 0; i < 8; i++)
#pragma unroll
                for (int j = 0; j < 8; j++)
                    acc[i][j] += ra[i] * rb[j];
        }
        if (more) {
            __syncthreads();
#pragma unroll
            for (int r = 0; r < 2; r++) {
                int row = lrow + r * 64;
                As[lkq+0][row]=pa[r].x; As[lkq+1][row]=pa[r].y;
                As[lkq+2][row]=pa[r].z; As[lkq+3][row]=pa[r].w;
                Bs[lkq+0][row]=pb[r].x; Bs[lkq+1][row]=pb[r].y;
                Bs[lkq+2][row]=pb[r].z; Bs[lkq+3][row]=pb[r].w;
            }
            __syncthreads();
        }
    }

    float* Yb = Y + (size_t)(blockIdx.y * BM + ty * 8) * GN + blockIdx.x * BN;
#pragma unroll
    for (int i = 0; i < 8; i++) {
        *(float4*)(Yb + (size_t)i * GN + tx*4)      = make_float4(acc[i][0], acc[i][1], acc[i][2], acc[i][3]);
        *(float4*)(Yb + (size_t)i * GN + 64 + tx*4) = make_float4(acc[i][4], acc[i][5], acc[i][6], acc[i][7]);
    }
}

// ---------------------------------------------------------------------------
// Attention v2: block-GEMM structure.
// 256 threads as 16(tx) x 16(ty); microtile 8 q-rows (ty*8) x 4 key-cols (tx*4).
// Q,K staged transposed (k-major) in smem with XOR swizzle so transpose writes
// are <=2-way conflicted and hot-loop LDS.128 reads are conflict-free.
// Online softmax in registers (shfl row reduce over 16 tx lanes).
// P staged through swizzled smem for the PV GEMM.
// ---------------------------------------------------------------------------
#define AQ 128
#define AK 64
#define KST 68    // KsT / Vs stride
#define QST 132   // QsT / PsT stride
#define SWZ(k) ((((k) >> 2) & 7) << 2)

__global__ __launch_bounds__(256, 2) void attn2(const float* __restrict__ gQ,
                                                const float* __restrict__ gK,
                                                const float* __restrict__ gV,
                                                const int*   __restrict__ mask,
                                                float* __restrict__ gO) {
    extern __shared__ float sm[];
    float* QsT = sm;                    // [64][QST]
    float* KsT = QsT + DH_ * QST;       // [64][KST]
    float* Vs  = KsT + DH_ * KST;       // [64][KST]
    float* PsT = Vs  + AK  * KST;       // [64][QST]
    float* Msk = PsT + AK  * QST;       // [64]

    const int t  = threadIdx.x;
    const int tx = t & 15;
    const int ty = t >> 4;
    const int h  = blockIdx.y;
    const int b  = blockIdx.z;
    const int qb = gridDim.x - 1 - blockIdx.x;   // heavy blocks first
    const int r0 = qb * AQ;

    // ---- load Q block transposed + swizzled (once) ----
#pragma unroll
    for (int w = 0; w < 8; w++) {
        int idx = t + w * 256;               // 128 rows x 16 float4
        int r  = idx >> 4;
        int c4 = idx & 15;
        float4 qv = *(const float4*)(gQ + ((size_t)(b * S_ + r0 + r)) * D_ + h * DH_ + c4 * 4);
        int k = c4 * 4, sw = (c4 & 7) << 2;  // SWZ(k) for k..k+3
        QsT[(k+0)*QST + (r ^ sw)] = qv.x;
        QsT[(k+1)*QST + (r ^ sw)] = qv.y;
        QsT[(k+2)*QST + (r ^ sw)] = qv.z;
        QsT[(k+3)*QST + (r ^ sw)] = qv.w;
    }

    float of[8][4];
    float m[8], lp[8];
#pragma unroll
    for (int i = 0; i < 8; i++) {
        m[i] = -1e30f; lp[i] = 0.0f;
#pragma unroll
        for (int q = 0; q < 4; q++) of[i][q] = 0.0f;
    }

    for (int t0 = 0; t0 < r0 + AQ; t0 += AK) {
        __syncthreads();   // prev PV done; Q ready on first iter
        // ---- load K (transposed+swizzled), V (natural), mask ----
#pragma unroll
        for (int w = 0; w < 4; w++) {
            int idx = t + w * 256;           // 64 rows x 16 float4
            int j  = idx >> 4;
            int c4 = idx & 15;
            size_t base = ((size_t)(b * S_ + t0 + j)) * D_ + h * DH_ + c4 * 4;
            float4 kv = *(const float4*)(gK + base);
            int k = c4 * 4, sw = (c4 & 7) << 2;
            KsT[(k+0)*KST + (j ^ sw)] = kv.x;
            KsT[(k+1)*KST + (j ^ sw)] = kv.y;
            KsT[(k+2)*KST + (j ^ sw)] = kv.z;
            KsT[(k+3)*KST + (j ^ sw)] = kv.w;
            *(float4*)&Vs[j * KST + c4 * 4] = *(const float4*)(gV + base);
        }
        if (t < AK) Msk[t] = (mask[b * S_ + t0 + t] == 0) ? NEGV : 0.0f;
        __syncthreads();

        // ---- QK^T: S[128x64] microtiled ----
        float sacc[8][4];
#pragma unroll
        for (int i = 0; i < 8; i++)
#pragma unroll
            for (int q = 0; q < 4; q++) sacc[i][q] = 0.0f;

#pragma unroll 8
        for (int kk = 0; kk < DH_; kk++) {
            int sw = SWZ(kk);
            float ra[8], rb[4];
            *(float4*)&ra[0] = *(const float4*)&QsT[kk*QST + ((ty*8)   ^ sw)];
            *(float4*)&ra[4] = *(const float4*)&QsT[kk*QST + ((ty*8+4) ^ sw)];
            *(float4*)&rb[0] = *(const float4*)&KsT[kk*KST + ((tx*4)   ^ sw)];
#pragma unroll
            for (int i = 0; i < 8; i++)
#pragma unroll
                for (int q = 0; q < 4; q++)
                    sacc[i][q] += ra[i] * rb[q];
        }

        // ---- masking + online softmax ----
        const bool diag = (t0 + AK) > (r0 + 1);
#pragma unroll
        for (int i = 0; i < 8; i++) {
            int row = r0 + ty * 8 + i;
            float tm = -1e30f;
#pragma unroll
            for (int q = 0; q < 4; q++) {
                float s = sacc[i][q] * 0.125f + Msk[tx*4+q];
                if (diag && (t0 + tx*4 + q > row)) s = NEGV;
                sacc[i][q] = s;
                tm = fmaxf(tm, s);
            }
#pragma unroll
            for (int o = 1; o < 16; o <<= 1)
                tm = fmaxf(tm, __shfl_xor_sync(0xffffffffu, tm, o));
            float mn = fmaxf(m[i], tm);
            float corr = __expf(m[i] - mn);
            m[i] = mn;
            lp[i] *= corr;
#pragma unroll
            for (int q = 0; q < 4; q++) {
                of[i][q] *= corr;
                float p = __expf(sacc[i][q] - mn);
                sacc[i][q] = p;
                lp[i] += p;
            }
        }

        // ---- stage P transposed+swizzled ----
#pragma unroll
        for (int q = 0; q < 4; q++) {
            int j = tx * 4 + q, sw = (tx & 7) << 2;   // SWZ(j) since j>>2 == tx
#pragma unroll
            for (int i = 0; i < 8; i++)
                PsT[j * QST + ((ty*8+i) ^ sw)] = sacc[i][q];
        }
        __syncthreads();

        // ---- PV: O[128x64] microtiled over keys ----
#pragma unroll 8
        for (int j = 0; j < AK; j++) {
            int sw = SWZ(j);
            float ra[8];
            *(float4*)&ra[0] = *(const float4*)&PsT[j*QST + ((ty*8)   ^ sw)];
            *(float4*)&ra[4] = *(const float4*)&PsT[j*QST + ((ty*8+4) ^ sw)];
            float4 rb = *(const float4*)&Vs[j * KST + tx * 4];
#pragma unroll
            for (int i = 0; i < 8; i++) {
                of[i][0] += ra[i] * rb.x;
                of[i][1] += ra[i] * rb.y;
                of[i][2] += ra[i] * rb.z;
                of[i][3] += ra[i] * rb.w;
            }
        }
    }

    // ---- finalize: reduce l across the 16 tx lanes, normalize, store ----
#pragma unroll
    for (int i = 0; i < 8; i++) {
        float l = lp[i];
#pragma unroll
        for (int o = 1; o < 16; o <<= 1)
            l += __shfl_xor_sync(0xffffffffu, l, o);
        float inv = 1.0f / l;
        float* orow = gO + ((size_t)(b * S_ + r0 + ty*8 + i)) * D_ + h * DH_ + tx * 4;
        *(float4*)orow = make_float4(of[i][0]*inv, of[i][1]*inv, of[i][2]*inv, of[i][3]*inv);
    }
}

// ---------------------------------------------------------------------------
extern "C" void kernel_launch(void* const* d_in, const int* in_sizes, int n_in,
                              void* d_out, int out_size) {
    const float* q    = (const float*)d_in[0];
    const float* k    = (const float*)d_in[1];
    const float* v    = (const float*)d_in[2];
    const int*   mask = (const int*)  d_in[3];
    const float* Wq   = (const float*)d_in[4];
    const float* Wk   = (const float*)d_in[5];
    const float* Wv   = (const float*)d_in[6];
    const float* Wo   = (const float*)d_in[7];
    float* out = (float*)d_out;

    float *Qp, *Kp, *Vp, *Op;
    cudaGetSymbolAddress((void**)&Qp, g_Q);
    cudaGetSymbolAddress((void**)&Kp, g_K);
    cudaGetSymbolAddress((void**)&Vp, g_V);
    cudaGetSymbolAddress((void**)&Op, g_O);

    dim3 ggrid(GN / BN, GM / BM);   // (8, 32)

    sgemm_nt<<<ggrid, 256>>>(q, Wq, Qp);
    sgemm_nt<<<ggrid, 256>>>(k, Wk, Kp);
    sgemm_nt<<<ggrid, 256>>>(v, Wv, Vp);

    size_t smem = (size_t)(DH_*QST + DH_*KST + AK*KST + AK*QST + AK) * sizeof(float);
    cudaFuncSetAttribute(attn2, cudaFuncAttributeMaxDynamicSharedMemorySize, (int)smem);
    attn2<<<dim3(S_ / AQ, H_, B_), 256, smem>>>(Qp, Kp, Vp, mask, Op);

    sgemm_nt<<<ggrid, 256>>>(Op, Wo, out);
}

// round 12
// speedup vs baseline: 1.5465x; 1.1839x over previous
#include <cuda_runtime.h>
#include <cstdint>

#define B_  2
#define S_  2048
#define D_  1024
#define H_  16
#define DH_ 64
#define NEGV -1000000000.0f

// Scratch (static __device__ — allocation-free per harness rules)
__device__ float g_Q[B_*S_*D_];
__device__ float g_K[B_*S_*D_];
__device__ float g_V[B_*S_*D_];
__device__ float g_O[B_*S_*D_];

// ===========================================================================
// Tensor-core GEMM via mma.sync (bf16 hi/lo split, fp32 accumulate).
//   Y[M,N] = X[M,K] * W[N,K]^T      (both K-major -> NT ldmatrix, no .trans)
// 128x128 CTA tile, K-stage 32, 8 warps (2x4), warp tile 64x32,
// 4x4 m16n8k16 tiles, 3 split terms (hh + hl + lh).
// smem row = 128B: [ 32 bf16 hi | 32 bf16 lo ], Swizzle<3,4,3>.
// ===========================================================================
#define GM 4096
#define GN 1024
#define GK 1024
#define TM 128
#define TN 128
#define BKS 32
#define NSTG (GK / BKS)     // 32

__device__ __forceinline__ uint32_t smem_u32(const void* p) {
    uint32_t a;
    asm("{ .reg .u64 t; cvta.to.shared.u64 t, %1; cvt.u32.u64 %0, t; }" : "=r"(a) : "l"(p));
    return a;
}

__device__ __forceinline__ void ldsm4(uint32_t* r, uint32_t addr) {
    asm volatile("ldmatrix.sync.aligned.m8n8.x4.shared.b16 {%0,%1,%2,%3}, [%4];"
                 : "=r"(r[0]), "=r"(r[1]), "=r"(r[2]), "=r"(r[3]) : "r"(addr));
}
__device__ __forceinline__ void mma16816(float* d, const uint32_t* a,
                                         uint32_t b0, uint32_t b1) {
    asm volatile(
        "mma.sync.aligned.m16n8k16.row.col.f32.bf16.bf16.f32 "
        "{%0,%1,%2,%3}, {%4,%5,%6,%7}, {%8,%9}, {%0,%1,%2,%3};"
        : "+f"(d[0]), "+f"(d[1]), "+f"(d[2]), "+f"(d[3])
        : "r"(a[0]), "r"(a[1]), "r"(a[2]), "r"(a[3]), "r"(b0), "r"(b1));
}

// split 8 fp32 into 8 bf16-hi (uint4) + 8 bf16-lo (uint4)
__device__ __forceinline__ void split8(float4 a, float4 b, uint4& hi, uint4& lo) {
    asm("cvt.rn.bf16x2.f32 %0, %1, %2;" : "=r"(hi.x) : "f"(a.y), "f"(a.x));
    asm("cvt.rn.bf16x2.f32 %0, %1, %2;" : "=r"(hi.y) : "f"(a.w), "f"(a.z));
    asm("cvt.rn.bf16x2.f32 %0, %1, %2;" : "=r"(hi.z) : "f"(b.y), "f"(b.x));
    asm("cvt.rn.bf16x2.f32 %0, %1, %2;" : "=r"(hi.w) : "f"(b.w), "f"(b.z));
    float rx, ry, rz, rw;
    rx = a.x - __uint_as_float(hi.x << 16);
    ry = a.y - __uint_as_float(hi.x & 0xffff0000u);
    rz = a.z - __uint_as_float(hi.y << 16);
    rw = a.w - __uint_as_float(hi.y & 0xffff0000u);
    asm("cvt.rn.bf16x2.f32 %0, %1, %2;" : "=r"(lo.x) : "f"(ry), "f"(rx));
    asm("cvt.rn.bf16x2.f32 %0, %1, %2;" : "=r"(lo.y) : "f"(rw), "f"(rz));
    rx = b.x - __uint_as_float(hi.z << 16);
    ry = b.y - __uint_as_float(hi.z & 0xffff0000u);
    rz = b.z - __uint_as_float(hi.w << 16);
    rw = b.w - __uint_as_float(hi.w & 0xffff0000u);
    asm("cvt.rn.bf16x2.f32 %0, %1, %2;" : "=r"(lo.z) : "f"(ry), "f"(rx));
    asm("cvt.rn.bf16x2.f32 %0, %1, %2;" : "=r"(lo.w) : "f"(rw), "f"(rz));
}

__device__ __forceinline__ void sts16(uint32_t addr, uint4 v) {
    asm volatile("st.shared.v4.b32 [%0], {%1,%2,%3,%4};"
                 :: "r"(addr), "r"(v.x), "r"(v.y), "r"(v.z), "r"(v.w) : "memory");
}

__global__ __launch_bounds__(256, 1) void gemm_mma(const float* __restrict__ X,
                                                   const float* __restrict__ W,
                                                   float* __restrict__ Y) {
    __shared__ __align__(128) char smem[2 * TM * 128];   // A tile + B tile, 32KB
    const uint32_t sA = smem_u32(smem);
    const uint32_t sB = sA + TM * 128;

    const int t    = threadIdx.x;
    const int lane = t & 31;
    const int wid  = t >> 5;
    const int wm   = (wid >> 2) * 64;   // 0 | 64
    const int wn   = (wid & 3) * 32;    // 0,32,64,96

    const float* Xb = X + (size_t)blockIdx.y * TM * GK;
    const float* Wb = W + (size_t)blockIdx.x * TN * GK;

    // per-thread load item decode: 1024 items = {A,B} x 128 rows x 4 k-groups(8)
    int lrow[4], lkc[4], ltile[4];
    uint32_t ldst_h[4], ldst_l[4];
#pragma unroll
    for (int it = 0; it < 4; it++) {
        int idx  = t + it * 256;
        ltile[it] = idx >> 9;
        int rem  = idx & 511;
        lrow[it] = rem >> 2;
        lkc[it]  = rem & 3;
        uint32_t base = ltile[it] ? sB : sA;
        uint32_t r7   = lrow[it] & 7;
        ldst_h[it] = base + lrow[it] * 128 + ((lkc[it]       ^ r7) << 4);
        ldst_l[it] = base + lrow[it] * 128 + (((lkc[it] + 4) ^ r7) << 4);
    }

    float acc[4][4][4];
#pragma unroll
    for (int mt = 0; mt < 4; mt++)
#pragma unroll
        for (int nt = 0; nt < 4; nt++)
#pragma unroll
            for (int i = 0; i < 4; i++) acc[mt][nt][i] = 0.0f;

    // ldmatrix source addresses (chunk index varies by ks/hilo)
    // A: rows wm+mt*16+(lane&15), chunk = hilo*4 + ks*2 + (lane>>4)
    uint32_t aRow[4], bRow[2];
#pragma unroll
    for (int mt = 0; mt < 4; mt++) {
        int r = wm + mt * 16 + (lane & 15);
        aRow[mt] = sA + r * 128 + (((r & 7) ^ (lane >> 4)) << 4);  // chunk base ^(r&7), chunk bit0 = lane>>4
    }
#pragma unroll
    for (int np = 0; np < 2; np++) {
        int r = wn + np * 16 + (lane & 15);
        bRow[np] = sB + r * 128 + (((r & 7) ^ (lane >> 4)) << 4);
    }
    // NOTE: the XOR trick above only works because chunk = (lane>>4) + {0,2,4,6};
    // recompute exactly instead (cheap, correct):
#pragma unroll
    for (int mt = 0; mt < 4; mt++) {
        int r = wm + mt * 16 + (lane & 15);
        aRow[mt] = sA + r * 128;     // add swizzled chunk at use site
    }
#pragma unroll
    for (int np = 0; np < 2; np++) {
        int r = wn + np * 16 + (lane & 15);
        bRow[np] = sB + r * 128;
    }
    const int aR7[4] = { (wm + 0*16 + (lane & 15)) & 7, (wm + 1*16 + (lane & 15)) & 7,
                         (wm + 2*16 + (lane & 15)) & 7, (wm + 3*16 + (lane & 15)) & 7 };
    const int bR7[2] = { (wn + 0*16 + (lane & 15)) & 7, (wn + 1*16 + (lane & 15)) & 7 };
    const int lhalf = lane >> 4;

    // ---- stage 0: load + convert + store ----
#pragma unroll
    for (int it = 0; it < 4; it++) {
        const float* src = (ltile[it] ? Wb : Xb) + (size_t)lrow[it] * GK + lkc[it] * 8;
        float4 f0 = *(const float4*)(src);
        float4 f1 = *(const float4*)(src + 4);
        uint4 hi, lo;
        split8(f0, f1, hi, lo);
        sts16(ldst_h[it], hi);
        sts16(ldst_l[it], lo);
    }
    __syncthreads();

    float4 pf[4][2];
    for (int c = 0; c < NSTG; c++) {
        const bool more = (c + 1) < NSTG;
        if (more) {
            const int k0 = (c + 1) * BKS;
#pragma unroll
            for (int it = 0; it < 4; it++) {
                const float* src = (ltile[it] ? Wb : Xb) + (size_t)lrow[it] * GK + k0 + lkc[it] * 8;
                pf[it][0] = *(const float4*)(src);
                pf[it][1] = *(const float4*)(src + 4);
            }
        }

#pragma unroll
        for (int ks = 0; ks < 2; ks++) {
            const int ch_h = ks * 2 + lhalf;       // hi chunk
            const int ch_l = ch_h + 4;             // lo chunk
            uint32_t bh[2][4], bl[2][4];
#pragma unroll
            for (int np = 0; np < 2; np++) {
                ldsm4(bh[np], bRow[np] + ((ch_h ^ bR7[np]) << 4));
                ldsm4(bl[np], bRow[np] + ((ch_l ^ bR7[np]) << 4));
            }
#pragma unroll
            for (int mt = 0; mt < 4; mt++) {
                uint32_t ah[4], al[4];
                ldsm4(ah, aRow[mt] + ((ch_h ^ aR7[mt]) << 4));
                ldsm4(al, aRow[mt] + ((ch_l ^ aR7[mt]) << 4));
#pragma unroll
                for (int nt = 0; nt < 4; nt++) {
                    const int np = nt >> 1, od = nt & 1;
                    uint32_t b0h = bh[np][od], b1h = bh[np][2 + od];
                    uint32_t b0l = bl[np][od], b1l = bl[np][2 + od];
                    mma16816(acc[mt][nt], ah, b0h, b1h);   // hi*hi
                    mma16816(acc[mt][nt], ah, b0l, b1l);   // hi*lo
                    mma16816(acc[mt][nt], al, b0h, b1h);   // lo*hi
                }
            }
        }
        __syncthreads();
        if (more) {
#pragma unroll
            for (int it = 0; it < 4; it++) {
                uint4 hi, lo;
                split8(pf[it][0], pf[it][1], hi, lo);
                sts16(ldst_h[it], hi);
                sts16(ldst_l[it], lo);
            }
            __syncthreads();
        }
    }

    // ---- epilogue ----
    float* yb = Y + (size_t)(blockIdx.y * TM) * GN + blockIdx.x * TN;
#pragma unroll
    for (int mt = 0; mt < 4; mt++) {
        int r   = wm + mt * 16 + (lane >> 2);
#pragma unroll
        for (int nt = 0; nt < 4; nt++) {
            int col = wn + nt * 8 + (lane & 3) * 2;
            *(float2*)(yb + (size_t)r * GN + col)       = make_float2(acc[mt][nt][0], acc[mt][nt][1]);
            *(float2*)(yb + (size_t)(r + 8) * GN + col) = make_float2(acc[mt][nt][2], acc[mt][nt][3]);
        }
    }
}

// ---------------------------------------------------------------------------
// Attention v2 (unchanged): block-GEMM structure, fp32 CUDA cores.
// ---------------------------------------------------------------------------
#define AQ 128
#define AK 64
#define KST 68
#define QST 132
#define SWZ(k) ((((k) >> 2) & 7) << 2)

__global__ __launch_bounds__(256, 2) void attn2(const float* __restrict__ gQ,
                                                const float* __restrict__ gK,
                                                const float* __restrict__ gV,
                                                const int*   __restrict__ mask,
                                                float* __restrict__ gO) {
    extern __shared__ float sm[];
    float* QsT = sm;
    float* KsT = QsT + DH_ * QST;
    float* Vs  = KsT + DH_ * KST;
    float* PsT = Vs  + AK  * KST;
    float* Msk = PsT + AK  * QST;

    const int t  = threadIdx.x;
    const int tx = t & 15;
    const int ty = t >> 4;
    const int h  = blockIdx.y;
    const int b  = blockIdx.z;
    const int qb = gridDim.x - 1 - blockIdx.x;
    const int r0 = qb * AQ;

#pragma unroll
    for (int w = 0; w < 8; w++) {
        int idx = t + w * 256;
        int r  = idx >> 4;
        int c4 = idx & 15;
        float4 qv = *(const float4*)(gQ + ((size_t)(b * S_ + r0 + r)) * D_ + h * DH_ + c4 * 4);
        int k = c4 * 4, sw = (c4 & 7) << 2;
        QsT[(k+0)*QST + (r ^ sw)] = qv.x;
        QsT[(k+1)*QST + (r ^ sw)] = qv.y;
        QsT[(k+2)*QST + (r ^ sw)] = qv.z;
        QsT[(k+3)*QST + (r ^ sw)] = qv.w;
    }

    float of[8][4];
    float m[8], lp[8];
#pragma unroll
    for (int i = 0; i < 8; i++) {
        m[i] = -1e30f; lp[i] = 0.0f;
#pragma unroll
        for (int q = 0; q < 4; q++) of[i][q] = 0.0f;
    }

    for (int t0 = 0; t0 < r0 + AQ; t0 += AK) {
        __syncthreads();
#pragma unroll
        for (int w = 0; w < 4; w++) {
            int idx = t + w * 256;
            int j  = idx >> 4;
            int c4 = idx & 15;
            size_t base = ((size_t)(b * S_ + t0 + j)) * D_ + h * DH_ + c4 * 4;
            float4 kv = *(const float4*)(gK + base);
            int k = c4 * 4, sw = (c4 & 7) << 2;
            KsT[(k+0)*KST + (j ^ sw)] = kv.x;
            KsT[(k+1)*KST + (j ^ sw)] = kv.y;
            KsT[(k+2)*KST + (j ^ sw)] = kv.z;
            KsT[(k+3)*KST + (j ^ sw)] = kv.w;
            *(float4*)&Vs[j * KST + c4 * 4] = *(const float4*)(gV + base);
        }
        if (t < AK) Msk[t] = (mask[b * S_ + t0 + t] == 0) ? NEGV : 0.0f;
        __syncthreads();

        float sacc[8][4];
#pragma unroll
        for (int i = 0; i < 8; i++)
#pragma unroll
            for (int q = 0; q < 4; q++) sacc[i][q] = 0.0f;

#pragma unroll 8
        for (int kk = 0; kk < DH_; kk++) {
            int sw = SWZ(kk);
            float ra[8], rb[4];
            *(float4*)&ra[0] = *(const float4*)&QsT[kk*QST + ((ty*8)   ^ sw)];
            *(float4*)&ra[4] = *(const float4*)&QsT[kk*QST + ((ty*8+4) ^ sw)];
            *(float4*)&rb[0] = *(const float4*)&KsT[kk*KST + ((tx*4)   ^ sw)];
#pragma unroll
            for (int i = 0; i < 8; i++)
#pragma unroll
                for (int q = 0; q < 4; q++)
                    sacc[i][q] += ra[i] * rb[q];
        }

        const bool diag = (t0 + AK) > (r0 + 1);
#pragma unroll
        for (int i = 0; i < 8; i++) {
            int row = r0 + ty * 8 + i;
            float tm = -1e30f;
#pragma unroll
            for (int q = 0; q < 4; q++) {
                float s = sacc[i][q] * 0.125f + Msk[tx*4+q];
                if (diag && (t0 + tx*4 + q > row)) s = NEGV;
                sacc[i][q] = s;
                tm = fmaxf(tm, s);
            }
#pragma unroll
            for (int o = 1; o < 16; o <<= 1)
                tm = fmaxf(tm, __shfl_xor_sync(0xffffffffu, tm, o));
            float mn = fmaxf(m[i], tm);
            float corr = __expf(m[i] - mn);
            m[i] = mn;
            lp[i] *= corr;
#pragma unroll
            for (int q = 0; q < 4; q++) {
                of[i][q] *= corr;
                float p = __expf(sacc[i][q] - mn);
                sacc[i][q] = p;
                lp[i] += p;
            }
        }

#pragma unroll
        for (int q = 0; q < 4; q++) {
            int j = tx * 4 + q, sw = (tx & 7) << 2;
#pragma unroll
            for (int i = 0; i < 8; i++)
                PsT[j * QST + ((ty*8+i) ^ sw)] = sacc[i][q];
        }
        __syncthreads();

#pragma unroll 8
        for (int j = 0; j < AK; j++) {
            int sw = SWZ(j);
            float ra[8];
            *(float4*)&ra[0] = *(const float4*)&PsT[j*QST + ((ty*8)   ^ sw)];
            *(float4*)&ra[4] = *(const float4*)&PsT[j*QST + ((ty*8+4) ^ sw)];
            float4 rb = *(const float4*)&Vs[j * KST + tx * 4];
#pragma unroll
            for (int i = 0; i < 8; i++) {
                of[i][0] += ra[i] * rb.x;
                of[i][1] += ra[i] * rb.y;
                of[i][2] += ra[i] * rb.z;
                of[i][3] += ra[i] * rb.w;
            }
        }
    }

#pragma unroll
    for (int i = 0; i < 8; i++) {
        float l = lp[i];
#pragma unroll
        for (int o = 1; o < 16; o <<= 1)
            l += __shfl_xor_sync(0xffffffffu, l, o);
        float inv = 1.0f / l;
        float* orow = gO + ((size_t)(b * S_ + r0 + ty*8 + i)) * D_ + h * DH_ + tx * 4;
        *(float4*)orow = make_float4(of[i][0]*inv, of[i][1]*inv, of[i][2]*inv, of[i][3]*inv);
    }
}

// ---------------------------------------------------------------------------
extern "C" void kernel_launch(void* const* d_in, const int* in_sizes, int n_in,
                              void* d_out, int out_size) {
    const float* q    = (const float*)d_in[0];
    const float* k    = (const float*)d_in[1];
    const float* v    = (const float*)d_in[2];
    const int*   mask = (const int*)  d_in[3];
    const float* Wq   = (const float*)d_in[4];
    const float* Wk   = (const float*)d_in[5];
    const float* Wv   = (const float*)d_in[6];
    const float* Wo   = (const float*)d_in[7];
    float* out = (float*)d_out;

    float *Qp, *Kp, *Vp, *Op;
    cudaGetSymbolAddress((void**)&Qp, g_Q);
    cudaGetSymbolAddress((void**)&Kp, g_K);
    cudaGetSymbolAddress((void**)&Vp, g_V);
    cudaGetSymbolAddress((void**)&Op, g_O);

    dim3 ggrid(GN / TN, GM / TM);   // (8, 32)

    gemm_mma<<<ggrid, 256>>>(q, Wq, Qp);
    gemm_mma<<<ggrid, 256>>>(k, Wk, Kp);
    gemm_mma<<<ggrid, 256>>>(v, Wv, Vp);

    size_t smem = (size_t)(DH_*QST + DH_*KST + AK*KST + AK*QST + AK) * sizeof(float);
    cudaFuncSetAttribute(attn2, cudaFuncAttributeMaxDynamicSharedMemorySize, (int)smem);
    attn2<<<dim3(S_ / AQ, H_, B_), 256, smem>>>(Qp, Kp, Vp, mask, Op);

    gemm_mma<<<ggrid, 256>>>(Op, Wo, out);
}